// round 1
// baseline (speedup 1.0000x reference)
#include <cuda_runtime.h>

#define NC 256
#define NH 256
#define NW 256
#define NBOX 100

// Inter-kernel scratch (device globals — no allocation allowed)
__device__ float g_cx[NBOX], g_cy[NBOX], g_a[NBOX], g_r2[NBOX];
__device__ float g_wgt[NBOX][4];
__device__ int   g_off[NBOX][4];
__device__ float g_coef[4][NC];   // A, B1, B2, D per channel

// ---------------------------------------------------------------------------
// Kernel 1: score compaction + per-box params + grid_sample weights/offsets
// ---------------------------------------------------------------------------
__global__ void box_kernel(const float* __restrict__ boxes,
                           const float* __restrict__ scores) {
    __shared__ int s_idx[NBOX];
    int tid = threadIdx.x;
    if (tid == 0) {
        int cnt = 0;
        for (int i = 0; i < NBOX; i++)
            if (scores[i] > 0.0f) s_idx[cnt++] = i;
        for (int i = cnt; i < NBOX; i++) s_idx[i] = 0;   // nonzero fill_value=0
    }
    __syncthreads();
    if (tid < NBOX) {
        const float* b = boxes + (size_t)s_idx[tid] * 24;
        float lx = b[0], rx = b[0], ly = b[1], ry = b[1];
        #pragma unroll
        for (int k = 1; k < 8; k++) {
            float x = b[3*k], y = b[3*k + 1];
            lx = fminf(lx, x); rx = fmaxf(rx, x);
            ly = fminf(ly, y); ry = fmaxf(ry, y);
        }
        float cx  = ((lx + rx) * 0.5f + 128.0f) / 160.0f;
        float cy  = ((ly + ry) * 0.5f + 128.0f) / 160.0f;
        float bev = ((ry - ly) / 160.0f) * ((rx - lx) / 160.0f);
        float a   = 1.0f / (2.0f * bev * bev);
        g_cx[tid] = cx; g_cy[tid] = cy; g_a[tid] = a;
        g_r2[tid] = cx*cx + cy*cy;

        // grid_sample (bilinear, zero pad, align_corners=False)
        float ix = ((cx + 1.0f) * (float)NW - 1.0f) * 0.5f;
        float iy = ((cy + 1.0f) * (float)NH - 1.0f) * 0.5f;
        float x0f = floorf(ix), y0f = floorf(iy);
        float wx1 = ix - x0f, wx0 = 1.0f - wx1;
        float wy1 = iy - y0f, wy0 = 1.0f - wy1;
        int x0 = (int)x0f, y0 = (int)y0f, x1 = x0 + 1, y1 = y0 + 1;
        bool vx0 = (x0 >= 0 && x0 < NW), vx1 = (x1 >= 0 && x1 < NW);
        bool vy0 = (y0 >= 0 && y0 < NH), vy1 = (y1 >= 0 && y1 < NH);
        int cx0 = min(max(x0, 0), NW - 1), cx1 = min(max(x1, 0), NW - 1);
        int cyy0 = min(max(y0, 0), NH - 1), cyy1 = min(max(y1, 0), NH - 1);
        g_wgt[tid][0] = (vx0 && vy0) ? wx0 * wy0 : 0.0f;  g_off[tid][0] = cyy0*NW + cx0;
        g_wgt[tid][1] = (vx1 && vy0) ? wx1 * wy0 : 0.0f;  g_off[tid][1] = cyy0*NW + cx1;
        g_wgt[tid][2] = (vx0 && vy1) ? wx0 * wy1 : 0.0f;  g_off[tid][2] = cyy1*NW + cx0;
        g_wgt[tid][3] = (vx1 && vy1) ? wx1 * wy1 : 0.0f;  g_off[tid][3] = cyy1*NW + cx1;
    }
}

// ---------------------------------------------------------------------------
// Kernel 2: per-channel coefficients. One block per channel; thread t < 100
// handles box t (4 gathered loads), then 4-way block reduction.
// ---------------------------------------------------------------------------
__global__ void coef_kernel(const float* __restrict__ feat) {
    int c = blockIdx.x;
    int t = threadIdx.x;   // 128 threads
    float s0 = 0.f, s1 = 0.f, s2 = 0.f, s3 = 0.f;
    if (t < NBOX) {
        const float* fc = feat + (size_t)c * NH * NW;
        float v = g_wgt[t][0] * __ldg(fc + g_off[t][0])
                + g_wgt[t][1] * __ldg(fc + g_off[t][1])
                + g_wgt[t][2] * __ldg(fc + g_off[t][2])
                + g_wgt[t][3] * __ldg(fc + g_off[t][3]);
        float ta = v * g_a[t];
        s0 = ta;
        s1 = ta * g_cx[t];
        s2 = ta * g_cy[t];
        s3 = ta * g_r2[t];
    }
    __shared__ float4 red[128];
    red[t] = make_float4(s0, s1, s2, s3);
    __syncthreads();
    #pragma unroll
    for (int s = 64; s > 0; s >>= 1) {
        if (t < s) {
            float4 u = red[t], v4 = red[t + s];
            red[t] = make_float4(u.x + v4.x, u.y + v4.y, u.z + v4.z, u.w + v4.w);
        }
        __syncthreads();
    }
    if (t == 0) {
        const float inv = 1.0f / (float)NBOX;
        float4 r = red[0];
        g_coef[0][c] = r.x * inv;          // A
        g_coef[1][c] = 2.0f * r.y * inv;   // B1
        g_coef[2][c] = 2.0f * r.z * inv;   // B2
        g_coef[3][c] = r.w * inv;          // D
    }
}

// ---------------------------------------------------------------------------
// Kernel 3: out[c,h,w] = w*(w*A - B1) + (h*(h*A - B2) + D)
// Pure store-bound: one float4 per thread, 256 threads = 4 rows per block.
// ---------------------------------------------------------------------------
__global__ void out_kernel(float4* __restrict__ out) {
    int tid = threadIdx.x;
    int row = blockIdx.x * 4 + (tid >> 6);   // row = c*256 + h
    int c = row >> 8;
    int h = row & 255;
    float A  = g_coef[0][c];
    float B1 = g_coef[1][c];
    float B2 = g_coef[2][c];
    float D  = g_coef[3][c];
    float hf = (float)h;
    float base = fmaf(hf, fmaf(hf, A, -B2), D);
    float w0 = (float)((tid & 63) * 4);
    float4 r;
    float w;
    w = w0;          r.x = fmaf(w, fmaf(w, A, -B1), base);
    w = w0 + 1.0f;   r.y = fmaf(w, fmaf(w, A, -B1), base);
    w = w0 + 2.0f;   r.z = fmaf(w, fmaf(w, A, -B1), base);
    w = w0 + 3.0f;   r.w = fmaf(w, fmaf(w, A, -B1), base);
    out[(size_t)row * 64 + (tid & 63)] = r;
}

// ---------------------------------------------------------------------------
extern "C" void kernel_launch(void* const* d_in, const int* in_sizes, int n_in,
                              void* d_out, int out_size) {
    const float* boxes  = (const float*)d_in[0];   // [100,8,3]
    const float* scores = (const float*)d_in[1];   // [100]
    const float* feat   = (const float*)d_in[2];   // [1,256,256,256]
    float* out = (float*)d_out;                    // [1,256,256,256]

    box_kernel<<<1, 128>>>(boxes, scores);
    coef_kernel<<<NC, 128>>>(feat);
    out_kernel<<<(NC * NH) / 4, 256>>>((float4*)out);
    (void)in_sizes; (void)n_in; (void)out_size;
}